// round 14
// baseline (speedup 1.0000x reference)
#include <cuda_runtime.h>
#include <cuda_bf16.h>
#include <cstdint>
#include <cstddef>

#define NE 800000
#define NN 50000
#define IN_CH 128
#define HID 64
#define OUT_CH 128
#define NT 6250          // 128-edge tiles (stage1)
#define NT2 12500        // 64-edge tiles (stage2)
#define RS2 0.70710678118654752f

// ---- stage2 smem (bytes): per-group A buffers (64 rows x 400B, hi+lo),
//      shared W tiles (128 rows x 400B, hi+lo), bias ----
#define A_GRP 51200      // per-group A region (hi 25600 + lo 25600)
#define A_LOFF 25600
#define W_H 102400
#define W_L 153600
#define S_BV 204800
#define SMEM2 205312

// ---- stage1 smem (bytes), pitch 272B (136 bf16) ----
#define S1_A_H 0
#define S1_A_L 34816
#define S1_W_H 69632
#define S1_W_L 87040
#define SMEM1  104448

// Node hidden state (complex interleaved [NN][64] floats), 12.8 MB scratch.
__device__ float g_h[(size_t)NN * HID];
// Pre-split EA (bf16 hi/lo), written by stage1, read by stage2. 2 x 204.8 MB.
__device__ uint2 g_eh[(size_t)NE * 32];   // [e][32 uint2] = 128 bf16 hi
__device__ uint2 g_el[(size_t)NE * 32];   // [e][32 uint2] = 128 bf16 lo

// ---------------------------------------------------------------------------
// Helpers
// ---------------------------------------------------------------------------
__device__ __forceinline__ uint32_t smem_u32(const void* p) {
    uint32_t a;
    asm("{ .reg .u64 t; cvta.to.shared.u64 t, %1; cvt.u32.u64 %0, t; }"
        : "=r"(a) : "l"(p));
    return a;
}

__device__ __forceinline__ int detect_kind(const void* mraw, int* sflags) {
    if (threadIdx.x < 2) sflags[threadIdx.x] = 0;
    __syncthreads();
    int l1 = 0, l23 = 0;
    const unsigned char* m = (const unsigned char*)mraw;
    for (int i = threadIdx.x; i < 2048; i += blockDim.x) {
        unsigned char b = m[i];
        if (b) {
            int r = i & 3;
            if (r == 1) l1 = 1;
            else if (r >= 2) l23 = 1;
        }
    }
    if (l1) atomicOr(&sflags[0], 1);
    if (l23) atomicOr(&sflags[1], 1);
    __syncthreads();
    return sflags[0] ? 0 : (sflags[1] ? 2 : 1);
}
__device__ __forceinline__ bool read_mask(const void* m, int kind, int e) {
    if (kind == 0) return ((const unsigned char*)m)[e] != 0;
    if (kind == 1) return ((const int*)m)[e] != 0;
    return ((const float*)m)[e] != 0.0f;
}

// Packed hi/lo bf16 split (exact): hi = {bf16(f1), bf16(f0)}, lo = residuals.
__device__ __forceinline__ void bf16_split2(float f0, float f1,
                                            uint32_t& hi, uint32_t& lo) {
    uint32_t h;
    asm("cvt.rn.bf16x2.f32 %0, %1, %2;" : "=r"(h) : "f"(f1), "f"(f0));
    float r0 = f0 - __uint_as_float(h << 16);
    float r1 = f1 - __uint_as_float(h & 0xFFFF0000u);
    uint32_t lw;
    asm("cvt.rn.bf16x2.f32 %0, %1, %2;" : "=r"(lw) : "f"(r1), "f"(r0));
    hi = h;
    lo = lw;
}

__device__ __forceinline__ void mma16816(float* c, const uint32_t* a,
                                         const uint32_t* b) {
    asm volatile(
        "mma.sync.aligned.m16n8k16.row.col.f32.bf16.bf16.f32 "
        "{%0,%1,%2,%3}, {%4,%5,%6,%7}, {%8,%9}, {%0,%1,%2,%3};"
        : "+f"(c[0]), "+f"(c[1]), "+f"(c[2]), "+f"(c[3])
        : "r"(a[0]), "r"(a[1]), "r"(a[2]), "r"(a[3]), "r"(b[0]), "r"(b[1]));
}

#define LDSM4(r, addr)                                                         \
    asm volatile("ldmatrix.sync.aligned.m8n8.x4.shared.b16 {%0,%1,%2,%3}, [%4];"\
        : "=r"((r)[0]), "=r"((r)[1]), "=r"((r)[2]), "=r"((r)[3]) : "r"(addr))

#define CP_ASYNC8(dst, src)                                                    \
    asm volatile("cp.async.ca.shared.global [%0], [%1], 8;"                    \
                 :: "r"(dst), "l"(src) : "memory")
#define CP_ASYNC_COMMIT() asm volatile("cp.async.commit_group;" ::: "memory")
#define CP_ASYNC_WAIT0()  asm volatile("cp.async.wait_group 0;" ::: "memory")

__device__ __forceinline__ void red_v4(float* p, float a, float b, float c,
                                       float d) {
    asm volatile("red.global.add.v4.f32 [%0], {%1,%2,%3,%4};"
                 :: "l"(p), "f"(a), "f"(b), "f"(c), "f"(d) : "memory");
}

__device__ __forceinline__ void bar_grp(int id) {
    asm volatile("bar.sync %0, 256;" :: "r"(id) : "memory");
}

// lane-split metadata: lanes 0-7 load u(row), 8-15 v(row), 16-23 mask(row)
__device__ __forceinline__ int load_lane_meta(const int* __restrict__ ei,
                                              const void* __restrict__ m,
                                              int kind, int eb, int l) {
    if (l < 8) return ei[eb + l];
    if (l < 16) return ei[NE + eb + (l - 8)];
    if (l < 24) {
        int e = eb + (l - 16);
        if (kind == 0) return ((const unsigned char*)m)[e];
        if (kind == 1) return ((const int*)m)[e];
        return (((const float*)m)[e] != 0.0f) ? 1 : 0;
    }
    return 0;
}

// ---------------------------------------------------------------------------
// Stage 1 (mma.sync): z = (EA @ W_in^T), rotate + red.v4 scatter into g_h.
// Also dumps the EA hi/lo bf16 words to gmem for stage2 (bit-identical).
// ---------------------------------------------------------------------------
__global__ void __launch_bounds__(512, 2) stage1_kernel(
    const float* __restrict__ ea, const float* __restrict__ Win,
    const int* __restrict__ ei, const void* __restrict__ mraw)
{
    extern __shared__ __align__(16) char sm1[];
    __shared__ int sflags[2];
    const int tid = threadIdx.x, w = tid >> 5, l = tid & 31;
    const int kind = detect_kind(mraw, sflags);
    const uint32_t sb = smem_u32(sm1);

    for (int x = tid; x < 64 * 64; x += 512) {
        int n = x >> 6, kp = x & 63;
        float2 wv = *(const float2*)(Win + n * IN_CH + 2 * kp);
        uint32_t hi, lo;
        bf16_split2(wv.x, wv.y, hi, lo);
        uint32_t off = (uint32_t)(n * 272 + 4 * kp);
        *(uint32_t*)(sm1 + S1_W_H + off) = hi;
        *(uint32_t*)(sm1 + S1_W_L + off) = lo;
    }

    const int wr = w >> 2, wc = w & 3;
    const int rowb = wr * 32, colb = wc * 16;
    const int g = l >> 2, tig = l & 3;
    const uint32_t a_sub = (uint32_t)((rowb + ((l >> 3) & 1) * 8 + (l & 7)) * 272
                                      + (l >> 4) * 16);
    const uint32_t b_sub = (uint32_t)((colb + ((l >> 4) & 1) * 8 + (l & 7)) * 272
                                      + ((l >> 3) & 1) * 16);
    float* zt = (float*)(sm1 + S1_A_H);   // reused as z tile [128][68] fp32

    for (int t = blockIdx.x; t < NT; t += gridDim.x) {
        __syncthreads();   // protect A_H (z of previous tile) until scatter done
        #pragma unroll 2
        for (int rr = 0; rr < 8; rr++) {
            int r = w * 8 + rr, e = t * 128 + r;
            float4 a4 = *(const float4*)(ea + (size_t)e * IN_CH + 4 * l);
            uint2 hv2, lv2;
            bf16_split2(a4.x, a4.y, hv2.x, lv2.x);
            bf16_split2(a4.z, a4.w, hv2.y, lv2.y);
            uint32_t off = (uint32_t)(r * 272 + 8 * l);
            *(uint2*)(sm1 + S1_A_H + off) = hv2;
            *(uint2*)(sm1 + S1_A_L + off) = lv2;
            // dump split EA for stage2 (fire-and-forget STG.64)
            g_eh[(size_t)e * 32 + l] = hv2;
            g_el[(size_t)e * 32 + l] = lv2;
        }
        __syncthreads();

        float acc[2][2][4];
        #pragma unroll
        for (int mf = 0; mf < 2; mf++)
            #pragma unroll
            for (int nf = 0; nf < 2; nf++)
                #pragma unroll
                for (int i = 0; i < 4; i++) acc[mf][nf][i] = 0.f;

        #pragma unroll 1
        for (int pass = 0; pass < 3; pass++) {
            uint32_t Ab = sb + (pass == 1 ? S1_A_L : S1_A_H);
            uint32_t Bb = sb + (pass == 2 ? S1_W_L : S1_W_H);
            uint32_t aa0 = Ab + a_sub, aa1 = aa0 + 16 * 272;
            uint32_t ba = Bb + b_sub;
            #pragma unroll
            for (int ks = 0; ks < 8; ks++) {
                uint32_t A0[4], A1[4], B0[4];
                LDSM4(A0, aa0);
                LDSM4(A1, aa1);
                LDSM4(B0, ba);
                mma16816(acc[0][0], A0, B0);
                mma16816(acc[0][1], A0, B0 + 2);
                mma16816(acc[1][0], A1, B0);
                mma16816(acc[1][1], A1, B0 + 2);
                aa0 += 32; aa1 += 32; ba += 32;
            }
        }
        __syncthreads();   // all warps done reading A tiles -> reuse as z

        #pragma unroll
        for (int mf = 0; mf < 2; mf++) {
            int row = rowb + mf * 16 + g;
            #pragma unroll
            for (int nf = 0; nf < 2; nf++) {
                int n = colb + nf * 8 + 2 * tig;
                *(float2*)(zt + row * 68 + n) =
                    make_float2(acc[mf][nf][0], acc[mf][nf][1]);
                *(float2*)(zt + (row + 8) * 68 + n) =
                    make_float2(acc[mf][nf][2], acc[mf][nf][3]);
            }
        }
        __syncthreads();

        {
            int el = tid >> 2, q = tid & 3;
            int e = t * 128 + el;
            int u = ei[e], v = ei[NE + e];
            bool und = read_mask(mraw, kind, e);
            float cc, ss, dinv;
            if (und) { cc = 1.0f; ss = 0.0f; dinv = (u == v) ? 0.0f : RS2; }
            else     { cc = RS2;  ss = RS2;  dinv = RS2; }
            if (dinv != 0.0f) {
                const float* zr = zt + el * 68 + 16 * q;
                float* hv = g_h + (size_t)v * HID + 16 * q;
                float* hu = g_h + (size_t)u * HID + 16 * q;
                #pragma unroll
                for (int j = 0; j < 4; j++) {
                    float4 z4 = *(const float4*)(zr + 4 * j);
                    float r0 = z4.x * dinv, i0 = z4.y * dinv;
                    float r1 = z4.z * dinv, i1 = z4.w * dinv;
                    red_v4(hv + 4 * j,
                           fmaf(cc, r0, ss * i0), fmaf(cc, i0, -ss * r0),
                           fmaf(cc, r1, ss * i1), fmaf(cc, i1, -ss * r1));
                    red_v4(hu + 4 * j,
                           fmaf(-cc, r0, ss * i0), fmaf(-cc, i0, -ss * r0),
                           fmaf(-cc, r1, ss * i1), fmaf(-cc, i1, -ss * r1));
                }
            }
        }
    }
}

// ---------------------------------------------------------------------------
// Stage 2: two-group ping-pong + tensor-phase mutex. Phase A now:
//   (1) issue g_h gathers, (2) cp.async the pre-split EA rows straight to
//   smem (no regs, no dependent STS), (3) Y build covers the copy latency,
//   (4) wait + barrier. Fused 3-pass hi/lo MMA unchanged.
// ---------------------------------------------------------------------------
__global__ void __launch_bounds__(512, 1) stage2_kernel(
    const float* __restrict__ Wout, const float* __restrict__ Wskip,
    const float* __restrict__ bskip, const float* __restrict__ bias,
    const int* __restrict__ ei, const void* __restrict__ mraw,
    float* __restrict__ out)
{
    extern __shared__ __align__(16) char sm[];
    __shared__ int sflags[2];
    __shared__ int s_sync[3];   // [0]=turn, [1]=done grp0, [2]=done grp1
    const int tid = threadIdx.x, l = tid & 31;
    const int kind = detect_kind(mraw, sflags);
    const uint32_t sb = smem_u32(sm);
    float* bv = (float*)(sm + S_BV);

    if (tid < 3) s_sync[tid] = 0;

    for (int x = tid; x < 128 * 32; x += 512) {         // W_out: k 0..63
        int n = x >> 5, kp = x & 31;
        float2 wv = *(const float2*)(Wout + n * HID + 2 * kp);
        uint32_t hi, lo;
        bf16_split2(wv.x, wv.y, hi, lo);
        uint32_t off = (uint32_t)(n * 400 + 4 * kp);
        *(uint32_t*)(sm + W_H + off) = hi;
        *(uint32_t*)(sm + W_L + off) = lo;
    }
    for (int x = tid; x < 128 * 64; x += 512) {         // W_skip: k 64..191
        int n = x >> 6, kp = x & 63;
        float2 wv = *(const float2*)(Wskip + n * IN_CH + 2 * kp);
        uint32_t hi, lo;
        bf16_split2(wv.x, wv.y, hi, lo);
        uint32_t off = (uint32_t)(n * 400 + 128 + 4 * kp);
        *(uint32_t*)(sm + W_H + off) = hi;
        *(uint32_t*)(sm + W_L + off) = lo;
    }
    if (tid < 128) bv[tid] = bskip[tid] + bias[tid];
    __syncthreads();

    const int grp = tid >> 8;            // 0 or 1
    const int gtid = tid & 255;
    const int w8 = (tid >> 5) & 7;
    const int barid = grp + 1;
    const uint32_t aBase = sb + (uint32_t)grp * A_GRP;

    const int wr = w8 >> 2, wc = w8 & 3; // 2x4 warp grid over 64x128 output
    const int rowb = wr * 32, colb = wc * 32;
    const int g = l >> 2, tig = l & 3;
    const uint32_t a_sub = (uint32_t)((rowb + ((l >> 3) & 1) * 8 + (l & 7)) * 400
                                      + (l >> 4) * 16);
    const uint32_t b_sub = (uint32_t)((colb + ((l >> 4) & 1) * 8 + (l & 7)) * 400
                                      + ((l >> 3) & 1) * 16);

    const int t0 = blockIdx.x * 2 + grp;
    const int tstride = gridDim.x * 2;
    int pre = 0;
    if (t0 < NT2)
        pre = load_lane_meta(ei, mraw, kind, t0 * 64 + w8 * 8, l);

    for (int t = t0; t < NT2; t += tstride) {
        // ---- Phase A ----
        // (1) issue gathers
        float2 phv[8], phu[8];
        #pragma unroll
        for (int r = 0; r < 8; r++) {
            int u = __shfl_sync(0xffffffffu, pre, r);
            int v = __shfl_sync(0xffffffffu, pre, r + 8);
            phv[r] = *(const float2*)(g_h + (size_t)v * HID + 2 * l);
            phu[r] = *(const float2*)(g_h + (size_t)u * HID + 2 * l);
        }
        // (2) cp.async the pre-split EA rows directly into smem
        #pragma unroll
        for (int rr = 0; rr < 8; rr++) {
            size_t e = (size_t)(t * 64 + w8 * 8 + rr);
            uint32_t dst = aBase + (uint32_t)((w8 * 8 + rr) * 400 + 128 + 8 * l);
            CP_ASYNC8(dst, (const void*)&g_eh[e * 32 + l]);
            CP_ASYNC8(dst + A_LOFF, (const void*)&g_el[e * 32 + l]);
        }
        CP_ASYNC_COMMIT();
        // (3) Y build (covers the async-copy latency)
        #pragma unroll
        for (int rq = 0; rq < 8; rq++) {
            int r = w8 * 8 + rq;
            int u = __shfl_sync(0xffffffffu, pre, rq);
            int v = __shfl_sync(0xffffffffu, pre, rq + 8);
            int mm = __shfl_sync(0xffffffffu, pre, rq + 16);
            float cc, ss, dinv;
            if (mm) { cc = 1.0f; ss = 0.0f; dinv = (u == v) ? 0.0f : RS2; }
            else    { cc = RS2;  ss = RS2;  dinv = RS2; }
            float av = fmaxf(phv[rq].x, 0.f), bvv = fmaxf(phv[rq].y, 0.f);
            float au = fmaxf(phu[rq].x, 0.f), bu  = fmaxf(phu[rq].y, 0.f);
            float yr = dinv * (cc * (av - au) - ss * (bvv + bu));
            float yi = dinv * (cc * (bvv - bu) + ss * (av + au));
            uint32_t yh, yl;
            bf16_split2(yr, yi, yh, yl);
            uint32_t off2 = (uint32_t)(r * 400 + 4 * l);
            *(uint32_t*)(sm + (aBase - sb) + off2) = yh;
            *(uint32_t*)(sm + (aBase - sb) + A_LOFF + off2) = yl;
        }
        // (4) prefetch next tile's indices, drain copies, group barrier
        const int tn = t + tstride;
        pre = (tn < NT2) ? load_lane_meta(ei, mraw, kind, tn * 64 + w8 * 8, l) : 0;
        CP_ASYNC_WAIT0();
        bar_grp(barid);

        // ---- acquire tensor-phase ticket (perf-only mutex) ----
        if (gtid == 0) {
            volatile int* vs = s_sync;
            while (vs[0] != grp && vs[1 + (1 - grp)] == 0) { }
        }
        bar_grp(barid);

        // ---- Phase B: fused 3-pass hi/lo mma over K=192 ----
        float acc[2][4][4];
        #pragma unroll
        for (int mf = 0; mf < 2; mf++)
            #pragma unroll
            for (int nf = 0; nf < 4; nf++)
                #pragma unroll
                for (int i = 0; i < 4; i++) acc[mf][nf][i] = 0.f;

        {
            uint32_t aH0 = aBase + a_sub, aH1 = aH0 + 16 * 400;
            uint32_t aL0 = aBase + A_LOFF + a_sub, aL1 = aL0 + 16 * 400;
            uint32_t bH0 = sb + W_H + b_sub, bH1 = bH0 + 16 * 400;
            uint32_t bL0 = sb + W_L + b_sub, bL1 = bL0 + 16 * 400;
            #pragma unroll 2
            for (int ks = 0; ks < 12; ks++) {
                uint32_t AH0[4], AH1[4], AL0[4], AL1[4];
                uint32_t BH0[4], BH1[4], BL0[4], BL1[4];
                LDSM4(AH0, aH0);
                LDSM4(AH1, aH1);
                LDSM4(BH0, bH0);
                LDSM4(BH1, bH1);
                LDSM4(AL0, aL0);
                LDSM4(AL1, aL1);
                LDSM4(BL0, bL0);
                LDSM4(BL1, bL1);
                mma16816(acc[0][0], AH0, BH0);
                mma16816(acc[0][1], AH0, BH0 + 2);
                mma16816(acc[0][2], AH0, BH1);
                mma16816(acc[0][3], AH0, BH1 + 2);
                mma16816(acc[1][0], AH1, BH0);
                mma16816(acc[1][1], AH1, BH0 + 2);
                mma16816(acc[1][2], AH1, BH1);
                mma16816(acc[1][3], AH1, BH1 + 2);
                mma16816(acc[0][0], AL0, BH0);
                mma16816(acc[0][1], AL0, BH0 + 2);
                mma16816(acc[0][2], AL0, BH1);
                mma16816(acc[0][3], AL0, BH1 + 2);
                mma16816(acc[1][0], AL1, BH0);
                mma16816(acc[1][1], AL1, BH0 + 2);
                mma16816(acc[1][2], AL1, BH1);
                mma16816(acc[1][3], AL1, BH1 + 2);
                mma16816(acc[0][0], AH0, BL0);
                mma16816(acc[0][1], AH0, BL0 + 2);
                mma16816(acc[0][2], AH0, BL1);
                mma16816(acc[0][3], AH0, BL1 + 2);
                mma16816(acc[1][0], AH1, BL0);
                mma16816(acc[1][1], AH1, BL0 + 2);
                mma16816(acc[1][2], AH1, BL1);
                mma16816(acc[1][3], AH1, BL1 + 2);
                aH0 += 32; aH1 += 32; aL0 += 32; aL1 += 32;
                bH0 += 32; bH1 += 32; bL0 += 32; bL1 += 32;
            }
        }

        // ---- release ticket ----
        if (gtid == 0) ((volatile int*)s_sync)[0] = 1 - grp;

        // ---- Phase C: bias + coalesced stores ----
        #pragma unroll
        for (int mf = 0; mf < 2; mf++) {
            int e0 = t * 64 + rowb + mf * 16 + g;
            #pragma unroll
            for (int nf = 0; nf < 4; nf++) {
                int c = colb + nf * 8 + 2 * tig;
                float2 bb = *(const float2*)(bv + c);
                float2 v0, v1;
                v0.x = acc[mf][nf][0] + bb.x;
                v0.y = acc[mf][nf][1] + bb.y;
                v1.x = acc[mf][nf][2] + bb.x;
                v1.y = acc[mf][nf][3] + bb.y;
                *(float2*)(out + (size_t)e0 * OUT_CH + c) = v0;
                *(float2*)(out + (size_t)(e0 + 8) * OUT_CH + c) = v1;
            }
        }
        bar_grp(barid);   // A buffers free for next Phase A
    }

    // signal completion so the other group never waits on us again
    if (gtid == 0) ((volatile int*)s_sync)[1 + grp] = 1;
}

extern "C" void kernel_launch(void* const* d_in, const int* in_sizes, int n_in,
                              void* d_out, int out_size) {
    (void)in_sizes; (void)n_in; (void)out_size;
    const int*   ei    = (const int*)d_in[0];
    const void*  mask  = d_in[1];
    const float* ea    = (const float*)d_in[2];
    const float* Win   = (const float*)d_in[3];
    const float* Wout  = (const float*)d_in[4];
    const float* Wskip = (const float*)d_in[5];
    const float* bskip = (const float*)d_in[6];
    const float* bias  = (const float*)d_in[7];
    float* out = (float*)d_out;

    int dev = 0;
    cudaGetDevice(&dev);
    int sms = 148;
    cudaDeviceGetAttribute(&sms, cudaDevAttrMultiProcessorCount, dev);

    void* hptr = nullptr;
    cudaGetSymbolAddress(&hptr, g_h);

    cudaFuncSetAttribute(stage1_kernel,
                         cudaFuncAttributeMaxDynamicSharedMemorySize, SMEM1);
    cudaFuncSetAttribute(stage2_kernel,
                         cudaFuncAttributeMaxDynamicSharedMemorySize, SMEM2);

    cudaMemsetAsync(hptr, 0, sizeof(float) * (size_t)NN * HID);
    stage1_kernel<<<sms * 2, 512, SMEM1>>>(ea, Win, ei, mask);
    stage2_kernel<<<sms, 512, SMEM2>>>(Wout, Wskip, bskip, bias, ei, mask, out);
}

// round 15
// speedup vs baseline: 1.5870x; 1.5870x over previous
#include <cuda_runtime.h>
#include <cuda_fp16.h>
#include <cstdint>
#include <cstddef>

#define NE 800000
#define NN 50000
#define IN_CH 128
#define HID 64
#define OUT_CH 128
#define NT 6250          // 128-edge tiles (stage1)
#define NT2 12500        // 64-edge tiles (stage2)
#define RS2 0.70710678118654752f

// ---- stage2 smem (bytes): 2 group A buffers (64 rows x 400B fp16),
//      shared W tile (128 rows x 400B fp16), bias. 103KB -> 2 CTAs/SM ----
#define A_GRP 25600
#define W_F   51200
#define S_BV  102400
#define SMEM2 103424

// ---- stage1 smem (bytes), pitch 272B: A fp16 34816, W fp16 17408 ----
#define S1_A 0
#define S1_W 34816
#define SMEM1 52480

// Node hidden state (complex interleaved [NN][64] floats), 12.8 MB scratch.
__device__ float g_h[(size_t)NN * HID];
// Pre-converted fp16 EA, written by stage1, read by stage2. 204.8 MB.
__device__ uint2 g_ef[(size_t)NE * 32];   // [e][32 uint2] = 128 fp16

// ---------------------------------------------------------------------------
// Helpers
// ---------------------------------------------------------------------------
__device__ __forceinline__ uint32_t smem_u32(const void* p) {
    uint32_t a;
    asm("{ .reg .u64 t; cvta.to.shared.u64 t, %1; cvt.u32.u64 %0, t; }"
        : "=r"(a) : "l"(p));
    return a;
}

__device__ __forceinline__ int detect_kind(const void* mraw, int* sflags) {
    if (threadIdx.x < 2) sflags[threadIdx.x] = 0;
    __syncthreads();
    int l1 = 0, l23 = 0;
    const unsigned char* m = (const unsigned char*)mraw;
    for (int i = threadIdx.x; i < 2048; i += blockDim.x) {
        unsigned char b = m[i];
        if (b) {
            int r = i & 3;
            if (r == 1) l1 = 1;
            else if (r >= 2) l23 = 1;
        }
    }
    if (l1) atomicOr(&sflags[0], 1);
    if (l23) atomicOr(&sflags[1], 1);
    __syncthreads();
    return sflags[0] ? 0 : (sflags[1] ? 2 : 1);
}
__device__ __forceinline__ bool read_mask(const void* m, int kind, int e) {
    if (kind == 0) return ((const unsigned char*)m)[e] != 0;
    if (kind == 1) return ((const int*)m)[e] != 0;
    return ((const float*)m)[e] != 0.0f;
}

// pack two floats into fp16x2 (lower = f0, upper = f1)
__device__ __forceinline__ uint32_t f16x2(float f0, float f1) {
    uint32_t r;
    asm("cvt.rn.f16x2.f32 %0, %1, %2;" : "=r"(r) : "f"(f1), "f"(f0));
    return r;
}

__device__ __forceinline__ void mmaf16(float* c, const uint32_t* a,
                                       const uint32_t* b) {
    asm volatile(
        "mma.sync.aligned.m16n8k16.row.col.f32.f16.f16.f32 "
        "{%0,%1,%2,%3}, {%4,%5,%6,%7}, {%8,%9}, {%0,%1,%2,%3};"
        : "+f"(c[0]), "+f"(c[1]), "+f"(c[2]), "+f"(c[3])
        : "r"(a[0]), "r"(a[1]), "r"(a[2]), "r"(a[3]), "r"(b[0]), "r"(b[1]));
}

#define LDSM4(r, addr)                                                         \
    asm volatile("ldmatrix.sync.aligned.m8n8.x4.shared.b16 {%0,%1,%2,%3}, [%4];"\
        : "=r"((r)[0]), "=r"((r)[1]), "=r"((r)[2]), "=r"((r)[3]) : "r"(addr))

__device__ __forceinline__ void red_v4(float* p, float a, float b, float c,
                                       float d) {
    asm volatile("red.global.add.v4.f32 [%0], {%1,%2,%3,%4};"
                 :: "l"(p), "f"(a), "f"(b), "f"(c), "f"(d) : "memory");
}

__device__ __forceinline__ void bar_grp(int id) {
    asm volatile("bar.sync %0, 256;" :: "r"(id) : "memory");
}

// lane-split metadata: lanes 0-7 load u(row), 8-15 v(row), 16-23 mask(row)
__device__ __forceinline__ int load_lane_meta(const int* __restrict__ ei,
                                              const void* __restrict__ m,
                                              int kind, int eb, int l) {
    if (l < 8) return ei[eb + l];
    if (l < 16) return ei[NE + eb + (l - 8)];
    if (l < 24) {
        int e = eb + (l - 16);
        if (kind == 0) return ((const unsigned char*)m)[e];
        if (kind == 1) return ((const int*)m)[e];
        return (((const float*)m)[e] != 0.0f) ? 1 : 0;
    }
    return 0;
}

// ---------------------------------------------------------------------------
// Stage 1 (fp16 single-pass mma.sync): z = EA @ W_in^T, rotate + red.v4
// scatter into g_h. Also dumps fp16 EA to gmem for stage2.
// ---------------------------------------------------------------------------
__global__ void __launch_bounds__(512, 2) stage1_kernel(
    const float* __restrict__ ea, const float* __restrict__ Win,
    const int* __restrict__ ei, const void* __restrict__ mraw)
{
    extern __shared__ __align__(16) char sm1[];
    __shared__ int sflags[2];
    const int tid = threadIdx.x, w = tid >> 5, l = tid & 31;
    const int kind = detect_kind(mraw, sflags);
    const uint32_t sb = smem_u32(sm1);

    for (int x = tid; x < 64 * 64; x += 512) {       // W_in [64][128] fp16
        int n = x >> 6, kp = x & 63;
        float2 wv = *(const float2*)(Win + n * IN_CH + 2 * kp);
        *(uint32_t*)(sm1 + S1_W + (uint32_t)(n * 272 + 4 * kp)) =
            f16x2(wv.x, wv.y);
    }

    const int wr = w >> 2, wc = w & 3;
    const int rowb = wr * 32, colb = wc * 16;
    const int g = l >> 2, tig = l & 3;
    const uint32_t a_sub = (uint32_t)((rowb + ((l >> 3) & 1) * 8 + (l & 7)) * 272
                                      + (l >> 4) * 16);
    const uint32_t b_sub = (uint32_t)((colb + ((l >> 4) & 1) * 8 + (l & 7)) * 272
                                      + ((l >> 3) & 1) * 16);
    float* zt = (float*)(sm1 + S1_A);   // reused as z tile [128][68] fp32

    for (int t = blockIdx.x; t < NT; t += gridDim.x) {
        __syncthreads();   // protect A (z of previous tile) until scatter done
        #pragma unroll 2
        for (int rr = 0; rr < 8; rr++) {
            int r = w * 8 + rr, e = t * 128 + r;
            float4 a4 = *(const float4*)(ea + (size_t)e * IN_CH + 4 * l);
            uint2 hv2;
            hv2.x = f16x2(a4.x, a4.y);
            hv2.y = f16x2(a4.z, a4.w);
            *(uint2*)(sm1 + S1_A + (uint32_t)(r * 272 + 8 * l)) = hv2;
            g_ef[(size_t)e * 32 + l] = hv2;   // dump for stage2
        }
        __syncthreads();

        float acc[2][2][4];
        #pragma unroll
        for (int mf = 0; mf < 2; mf++)
            #pragma unroll
            for (int nf = 0; nf < 2; nf++)
                #pragma unroll
                for (int i = 0; i < 4; i++) acc[mf][nf][i] = 0.f;

        {
            uint32_t aa0 = sb + S1_A + a_sub, aa1 = aa0 + 16 * 272;
            uint32_t ba = sb + S1_W + b_sub;
            #pragma unroll
            for (int ks = 0; ks < 8; ks++) {
                uint32_t A0[4], A1[4], B0[4];
                LDSM4(A0, aa0);
                LDSM4(A1, aa1);
                LDSM4(B0, ba);
                mmaf16(acc[0][0], A0, B0);
                mmaf16(acc[0][1], A0, B0 + 2);
                mmaf16(acc[1][0], A1, B0);
                mmaf16(acc[1][1], A1, B0 + 2);
                aa0 += 32; aa1 += 32; ba += 32;
            }
        }
        __syncthreads();   // all warps done reading A tile -> reuse as z

        #pragma unroll
        for (int mf = 0; mf < 2; mf++) {
            int row = rowb + mf * 16 + g;
            #pragma unroll
            for (int nf = 0; nf < 2; nf++) {
                int n = colb + nf * 8 + 2 * tig;
                *(float2*)(zt + row * 68 + n) =
                    make_float2(acc[mf][nf][0], acc[mf][nf][1]);
                *(float2*)(zt + (row + 8) * 68 + n) =
                    make_float2(acc[mf][nf][2], acc[mf][nf][3]);
            }
        }
        __syncthreads();

        {
            int el = tid >> 2, q = tid & 3;
            int e = t * 128 + el;
            int u = ei[e], v = ei[NE + e];
            bool und = read_mask(mraw, kind, e);
            float cc, ss, dinv;
            if (und) { cc = 1.0f; ss = 0.0f; dinv = (u == v) ? 0.0f : RS2; }
            else     { cc = RS2;  ss = RS2;  dinv = RS2; }
            if (dinv != 0.0f) {
                const float* zr = zt + el * 68 + 16 * q;
                float* hv = g_h + (size_t)v * HID + 16 * q;
                float* hu = g_h + (size_t)u * HID + 16 * q;
                #pragma unroll
                for (int j = 0; j < 4; j++) {
                    float4 z4 = *(const float4*)(zr + 4 * j);
                    float r0 = z4.x * dinv, i0 = z4.y * dinv;
                    float r1 = z4.z * dinv, i1 = z4.w * dinv;
                    red_v4(hv + 4 * j,
                           fmaf(cc, r0, ss * i0), fmaf(cc, i0, -ss * r0),
                           fmaf(cc, r1, ss * i1), fmaf(cc, i1, -ss * r1));
                    red_v4(hu + 4 * j,
                           fmaf(-cc, r0, ss * i0), fmaf(-cc, i0, -ss * r0),
                           fmaf(-cc, r1, ss * i1), fmaf(-cc, i1, -ss * r1));
                }
            }
        }
    }
}

// ---------------------------------------------------------------------------
// Stage 2 (fp16 single-pass): two-group ping-pong + tensor-phase mutex,
// 2 CTAs/SM (103KB smem). A = [Y | EA_fp16] 64x192, B = [W_out | W_skip]
// fp16; D = A @ B^T in ONE pass (12 k-steps x 4 LDSM + 8 MMA per warp).
// ---------------------------------------------------------------------------
__global__ void __launch_bounds__(512, 2) stage2_kernel(
    const float* __restrict__ Wout, const float* __restrict__ Wskip,
    const float* __restrict__ bskip, const float* __restrict__ bias,
    const int* __restrict__ ei, const void* __restrict__ mraw,
    float* __restrict__ out)
{
    extern __shared__ __align__(16) char sm[];
    __shared__ int sflags[2];
    __shared__ int s_sync[3];   // [0]=turn, [1]=done grp0, [2]=done grp1
    const int tid = threadIdx.x, l = tid & 31;
    const int kind = detect_kind(mraw, sflags);
    const uint32_t sb = smem_u32(sm);
    float* bv = (float*)(sm + S_BV);

    if (tid < 3) s_sync[tid] = 0;

    for (int x = tid; x < 128 * 32; x += 512) {      // W_out: k 0..63
        int n = x >> 5, kp = x & 31;
        float2 wv = *(const float2*)(Wout + n * HID + 2 * kp);
        *(uint32_t*)(sm + W_F + (uint32_t)(n * 400 + 4 * kp)) =
            f16x2(wv.x, wv.y);
    }
    for (int x = tid; x < 128 * 64; x += 512) {      // W_skip: k 64..191
        int n = x >> 6, kp = x & 63;
        float2 wv = *(const float2*)(Wskip + n * IN_CH + 2 * kp);
        *(uint32_t*)(sm + W_F + (uint32_t)(n * 400 + 128 + 4 * kp)) =
            f16x2(wv.x, wv.y);
    }
    if (tid < 128) bv[tid] = bskip[tid] + bias[tid];
    __syncthreads();

    const int grp = tid >> 8;            // 0 or 1
    const int gtid = tid & 255;
    const int w8 = (tid >> 5) & 7;
    const int barid = grp + 1;
    const uint32_t aBase = sb + (uint32_t)grp * A_GRP;

    const int wr = w8 >> 2, wc = w8 & 3; // 2x4 warp grid over 64x128 output
    const int rowb = wr * 32, colb = wc * 32;
    const int g = l >> 2, tig = l & 3;
    const uint32_t a_sub = (uint32_t)((rowb + ((l >> 3) & 1) * 8 + (l & 7)) * 400
                                      + (l >> 4) * 16);
    const uint32_t b_sub = (uint32_t)((colb + ((l >> 4) & 1) * 8 + (l & 7)) * 400
                                      + ((l >> 3) & 1) * 16);

    const int t0 = blockIdx.x * 2 + grp;
    const int tstride = gridDim.x * 2;
    int pre = 0;
    if (t0 < NT2)
        pre = load_lane_meta(ei, mraw, kind, t0 * 64 + w8 * 8, l);

    for (int t = t0; t < NT2; t += tstride) {
        // ---- Phase A: gathers + fp16 EA streaming + Y build ----
        float2 phv[8], phu[8];
        #pragma unroll
        for (int r = 0; r < 8; r++) {
            int u = __shfl_sync(0xffffffffu, pre, r);
            int v = __shfl_sync(0xffffffffu, pre, r + 8);
            phv[r] = *(const float2*)(g_h + (size_t)v * HID + 2 * l);
            phu[r] = *(const float2*)(g_h + (size_t)u * HID + 2 * l);
        }
        #pragma unroll
        for (int b = 0; b < 2; b++) {
            uint2 eh[4];
            #pragma unroll
            for (int rr = 0; rr < 4; rr++) {
                size_t e = (size_t)(t * 64 + w8 * 8 + b * 4 + rr);
                eh[rr] = g_ef[e * 32 + l];
            }
            #pragma unroll
            for (int rr = 0; rr < 4; rr++) {
                int r = w8 * 8 + b * 4 + rr;
                *(uint2*)(sm + (aBase - sb)
                          + (uint32_t)(r * 400 + 128 + 8 * l)) = eh[rr];

                int rq = b * 4 + rr;
                int u = __shfl_sync(0xffffffffu, pre, rq);
                int v = __shfl_sync(0xffffffffu, pre, rq + 8);
                int mm = __shfl_sync(0xffffffffu, pre, rq + 16);
                float cc, ss, dinv;
                if (mm) { cc = 1.0f; ss = 0.0f; dinv = (u == v) ? 0.0f : RS2; }
                else    { cc = RS2;  ss = RS2;  dinv = RS2; }
                float av = fmaxf(phv[rq].x, 0.f), bvv = fmaxf(phv[rq].y, 0.f);
                float au = fmaxf(phu[rq].x, 0.f), bu  = fmaxf(phu[rq].y, 0.f);
                float yr = dinv * (cc * (av - au) - ss * (bvv + bu));
                float yi = dinv * (cc * (bvv - bu) + ss * (av + au));
                *(uint32_t*)(sm + (aBase - sb)
                             + (uint32_t)(r * 400 + 4 * l)) = f16x2(yr, yi);
            }
        }
        // prefetch next tile's indices (land during Phase B)
        const int tn = t + tstride;
        pre = (tn < NT2) ? load_lane_meta(ei, mraw, kind, tn * 64 + w8 * 8, l) : 0;
        bar_grp(barid);

        // ---- acquire tensor-phase ticket (perf-only mutex) ----
        if (gtid == 0) {
            volatile int* vs = s_sync;
            while (vs[0] != grp && vs[1 + (1 - grp)] == 0) { }
        }
        bar_grp(barid);

        // ---- Phase B: single-pass fp16 mma over K=192 ----
        float acc[2][4][4];
        #pragma unroll
        for (int mf = 0; mf < 2; mf++)
            #pragma unroll
            for (int nf = 0; nf < 4; nf++)
                #pragma unroll
                for (int i = 0; i < 4; i++) acc[mf][nf][i] = 0.f;

        {
            uint32_t aa0 = aBase + a_sub, aa1 = aa0 + 16 * 400;
            uint32_t bb0 = sb + W_F + b_sub, bb1 = bb0 + 16 * 400;
            #pragma unroll 4
            for (int ks = 0; ks < 12; ks++) {
                uint32_t A0[4], A1[4], B0[4], B1[4];
                LDSM4(A0, aa0);
                LDSM4(A1, aa1);
                LDSM4(B0, bb0);
                LDSM4(B1, bb1);
                mmaf16(acc[0][0], A0, B0);
                mmaf16(acc[0][1], A0, B0 + 2);
                mmaf16(acc[0][2], A0, B1);
                mmaf16(acc[0][3], A0, B1 + 2);
                mmaf16(acc[1][0], A1, B0);
                mmaf16(acc[1][1], A1, B0 + 2);
                mmaf16(acc[1][2], A1, B1);
                mmaf16(acc[1][3], A1, B1 + 2);
                aa0 += 32; aa1 += 32; bb0 += 32; bb1 += 32;
            }
        }

        // ---- release ticket ----
        if (gtid == 0) ((volatile int*)s_sync)[0] = 1 - grp;

        // ---- Phase C: bias + coalesced stores ----
        #pragma unroll
        for (int mf = 0; mf < 2; mf++) {
            int e0 = t * 64 + rowb + mf * 16 + g;
            #pragma unroll
            for (int nf = 0; nf < 4; nf++) {
                int c = colb + nf * 8 + 2 * tig;
                float2 bb = *(const float2*)(bv + c);
                float2 v0, v1;
                v0.x = acc[mf][nf][0] + bb.x;
                v0.y = acc[mf][nf][1] + bb.y;
                v1.x = acc[mf][nf][2] + bb.x;
                v1.y = acc[mf][nf][3] + bb.y;
                *(float2*)(out + (size_t)e0 * OUT_CH + c) = v0;
                *(float2*)(out + (size_t)(e0 + 8) * OUT_CH + c) = v1;
            }
        }
        bar_grp(barid);   // A buffer free for next Phase A
    }

    // signal completion so the other group never waits on us again
    if (gtid == 0) ((volatile int*)s_sync)[1 + grp] = 1;
}

extern "C" void kernel_launch(void* const* d_in, const int* in_sizes, int n_in,
                              void* d_out, int out_size) {
    (void)in_sizes; (void)n_in; (void)out_size;
    const int*   ei    = (const int*)d_in[0];
    const void*  mask  = d_in[1];
    const float* ea    = (const float*)d_in[2];
    const float* Win   = (const float*)d_in[3];
    const float* Wout  = (const float*)d_in[4];
    const float* Wskip = (const float*)d_in[5];
    const float* bskip = (const float*)d_in[6];
    const float* bias  = (const float*)d_in[7];
    float* out = (float*)d_out;

    int dev = 0;
    cudaGetDevice(&dev);
    int sms = 148;
    cudaDeviceGetAttribute(&sms, cudaDevAttrMultiProcessorCount, dev);

    void* hptr = nullptr;
    cudaGetSymbolAddress(&hptr, g_h);

    cudaFuncSetAttribute(stage1_kernel,
                         cudaFuncAttributeMaxDynamicSharedMemorySize, SMEM1);
    cudaFuncSetAttribute(stage2_kernel,
                         cudaFuncAttributeMaxDynamicSharedMemorySize, SMEM2);

    cudaMemsetAsync(hptr, 0, sizeof(float) * (size_t)NN * HID);
    stage1_kernel<<<sms * 2, 512, SMEM1>>>(ea, Win, ei, mask);
    stage2_kernel<<<sms * 2, 512, SMEM2>>>(Wout, Wskip, bskip, bias, ei, mask, out);
}

// round 16
// speedup vs baseline: 1.8403x; 1.1596x over previous
#include <cuda_runtime.h>
#include <cuda_fp16.h>
#include <cstdint>
#include <cstddef>

#define NE 800000
#define NN 50000
#define IN_CH 128
#define HID 64
#define OUT_CH 128
#define NT 6250          // 128-edge tiles (stage1)
#define NT2 12500        // 64-edge tiles (stage2)
#define RS2 0.70710678118654752f

// ---- stage2 smem (bytes): 2 group A buffers (64 rows x 400B fp16),
//      shared W tile (128 rows x 400B fp16), bias. 103KB -> 2 CTAs/SM ----
#define A_GRP 25600
#define W_F   51200
#define S_BV  102400
#define SMEM2 103424

// ---- stage1 smem (bytes), pitch 272B: A fp16 34816, W fp16 17408 ----
#define S1_A 0
#define S1_W 34816
#define SMEM1 52480

// Node hidden state (complex interleaved [NN][64] floats), 12.8 MB scratch.
__device__ float g_h[(size_t)NN * HID];
// Pre-converted fp16 EA, written by stage1, read by stage2. 204.8 MB.
__device__ uint2 g_ef[(size_t)NE * 32];   // [e][32 uint2] = 128 fp16, 256B/row

// ---------------------------------------------------------------------------
// Helpers
// ---------------------------------------------------------------------------
__device__ __forceinline__ uint32_t smem_u32(const void* p) {
    uint32_t a;
    asm("{ .reg .u64 t; cvta.to.shared.u64 t, %1; cvt.u32.u64 %0, t; }"
        : "=r"(a) : "l"(p));
    return a;
}

// Within-16 output-channel permutation so a lane's fragment pair (nf, nf+1)
// holds 4 consecutive actual columns: smem row s holds actual col a where
// s = nf*8 + 2t + j  <->  a = 4t + 2nf + j.
__device__ __forceinline__ int perm16(int a) {
    return ((a >> 1) & 1) * 8 + (a >> 2) * 2 + (a & 1);
}
__device__ __forceinline__ int permrow(int n) {
    return (n & ~15) | perm16(n & 15);
}

__device__ __forceinline__ int detect_kind(const void* mraw, int* sflags) {
    if (threadIdx.x < 2) sflags[threadIdx.x] = 0;
    __syncthreads();
    int l1 = 0, l23 = 0;
    const unsigned char* m = (const unsigned char*)mraw;
    for (int i = threadIdx.x; i < 2048; i += blockDim.x) {
        unsigned char b = m[i];
        if (b) {
            int r = i & 3;
            if (r == 1) l1 = 1;
            else if (r >= 2) l23 = 1;
        }
    }
    if (l1) atomicOr(&sflags[0], 1);
    if (l23) atomicOr(&sflags[1], 1);
    __syncthreads();
    return sflags[0] ? 0 : (sflags[1] ? 2 : 1);
}
__device__ __forceinline__ bool read_mask(const void* m, int kind, int e) {
    if (kind == 0) return ((const unsigned char*)m)[e] != 0;
    if (kind == 1) return ((const int*)m)[e] != 0;
    return ((const float*)m)[e] != 0.0f;
}

// pack two floats into fp16x2 (lower = f0, upper = f1)
__device__ __forceinline__ uint32_t f16x2(float f0, float f1) {
    uint32_t r;
    asm("cvt.rn.f16x2.f32 %0, %1, %2;" : "=r"(r) : "f"(f1), "f"(f0));
    return r;
}

__device__ __forceinline__ void mmaf16(float* c, const uint32_t* a,
                                       const uint32_t* b) {
    asm volatile(
        "mma.sync.aligned.m16n8k16.row.col.f32.f16.f16.f32 "
        "{%0,%1,%2,%3}, {%4,%5,%6,%7}, {%8,%9}, {%0,%1,%2,%3};"
        : "+f"(c[0]), "+f"(c[1]), "+f"(c[2]), "+f"(c[3])
        : "r"(a[0]), "r"(a[1]), "r"(a[2]), "r"(a[3]), "r"(b[0]), "r"(b[1]));
}

#define LDSM4(r, addr)                                                         \
    asm volatile("ldmatrix.sync.aligned.m8n8.x4.shared.b16 {%0,%1,%2,%3}, [%4];"\
        : "=r"((r)[0]), "=r"((r)[1]), "=r"((r)[2]), "=r"((r)[3]) : "r"(addr))

__device__ __forceinline__ void red_v4(float* p, float a, float b, float c,
                                       float d) {
    asm volatile("red.global.add.v4.f32 [%0], {%1,%2,%3,%4};"
                 :: "l"(p), "f"(a), "f"(b), "f"(c), "f"(d) : "memory");
}

__device__ __forceinline__ void bar_grp(int id) {
    asm volatile("bar.sync %0, 256;" :: "r"(id) : "memory");
}

// lane-split metadata: lanes 0-7 load u(row), 8-15 v(row), 16-23 mask(row)
__device__ __forceinline__ int load_lane_meta(const int* __restrict__ ei,
                                              const void* __restrict__ m,
                                              int kind, int eb, int l) {
    if (l < 8) return ei[eb + l];
    if (l < 16) return ei[NE + eb + (l - 8)];
    if (l < 24) {
        int e = eb + (l - 16);
        if (kind == 0) return ((const unsigned char*)m)[e];
        if (kind == 1) return ((const int*)m)[e];
        return (((const float*)m)[e] != 0.0f) ? 1 : 0;
    }
    return 0;
}

// ---------------------------------------------------------------------------
// Stage 1 (fp16 single-pass mma.sync): z = EA @ W_in^T (W_in col-permuted),
// rotate IN REGISTERS, red.v4 scatter straight from accumulators (no z smem
// round-trip; 2 barriers/tile instead of 4). Also dumps fp16 EA for stage2.
// ---------------------------------------------------------------------------
__global__ void __launch_bounds__(512, 2) stage1_kernel(
    const float* __restrict__ ea, const float* __restrict__ Win,
    const int* __restrict__ ei, const void* __restrict__ mraw)
{
    extern __shared__ __align__(16) char sm1[];
    __shared__ int sflags[2];
    const int tid = threadIdx.x, w = tid >> 5, l = tid & 31;
    const int kind = detect_kind(mraw, sflags);
    const uint32_t sb = smem_u32(sm1);

    for (int x = tid; x < 64 * 64; x += 512) {       // W_in [64][128] fp16
        int n = x >> 6, kp = x & 63;
        float2 wv = *(const float2*)(Win + n * IN_CH + 2 * kp);
        *(uint32_t*)(sm1 + S1_W + (uint32_t)(permrow(n) * 272 + 4 * kp)) =
            f16x2(wv.x, wv.y);
    }

    const int wr = w >> 2, wc = w & 3;
    const int rowb = wr * 32, colb = wc * 16;
    const int g = l >> 2, tig = l & 3;
    const uint32_t a_sub = (uint32_t)((rowb + ((l >> 3) & 1) * 8 + (l & 7)) * 272
                                      + (l >> 4) * 16);
    const uint32_t b_sub = (uint32_t)((colb + ((l >> 4) & 1) * 8 + (l & 7)) * 272
                                      + ((l >> 3) & 1) * 16);

    for (int t = blockIdx.x; t < NT; t += gridDim.x) {
        // ---- build A rows w*8..w*8+7 (fp16) + dump for stage2 ----
        #pragma unroll 2
        for (int rr = 0; rr < 8; rr++) {
            int r = w * 8 + rr, e = t * 128 + r;
            float4 a4 = *(const float4*)(ea + (size_t)e * IN_CH + 4 * l);
            uint2 hv2;
            hv2.x = f16x2(a4.x, a4.y);
            hv2.y = f16x2(a4.z, a4.w);
            *(uint2*)(sm1 + S1_A + (uint32_t)(r * 272 + 8 * l)) = hv2;
            g_ef[(size_t)e * 32 + l] = hv2;
        }
        // metadata for this warp's 32 MMA rows (lane l -> row rowb+l)
        int pu = ei[t * 128 + rowb + l];
        int pv = ei[NE + t * 128 + rowb + l];
        int pm = read_mask(mraw, kind, t * 128 + rowb + l) ? 1 : 0;
        __syncthreads();

        float acc[2][2][4];
        #pragma unroll
        for (int mf = 0; mf < 2; mf++)
            #pragma unroll
            for (int nf = 0; nf < 2; nf++)
                #pragma unroll
                for (int i = 0; i < 4; i++) acc[mf][nf][i] = 0.f;

        {
            uint32_t aa0 = sb + S1_A + a_sub, aa1 = aa0 + 16 * 272;
            uint32_t ba = sb + S1_W + b_sub;
            #pragma unroll
            for (int ks = 0; ks < 8; ks++) {
                uint32_t A0[4], A1[4], B0[4];
                LDSM4(A0, aa0);
                LDSM4(A1, aa1);
                LDSM4(B0, ba);
                mmaf16(acc[0][0], A0, B0);
                mmaf16(acc[0][1], A0, B0 + 2);
                mmaf16(acc[1][0], A1, B0);
                mmaf16(acc[1][1], A1, B0 + 2);
                aa0 += 32; aa1 += 32; ba += 32;
            }
        }

        // ---- register scatter: cols colb+4*tig..+3 (perm makes them
        //      consecutive), rows rowb + mf*16 + g + 8*rsel ----
        #pragma unroll
        for (int mf = 0; mf < 2; mf++) {
            #pragma unroll
            for (int rsel = 0; rsel < 2; rsel++) {
                int rloc = mf * 16 + g + rsel * 8;
                int u = __shfl_sync(0xffffffffu, pu, rloc);
                int v = __shfl_sync(0xffffffffu, pv, rloc);
                int mm = __shfl_sync(0xffffffffu, pm, rloc);
                float cc, ss, dinv;
                if (mm) { cc = 1.0f; ss = 0.0f; dinv = (u == v) ? 0.0f : RS2; }
                else    { cc = RS2;  ss = RS2;  dinv = RS2; }
                if (dinv != 0.0f) {
                    float r0 = acc[mf][0][2 * rsel] * dinv;
                    float i0 = acc[mf][0][2 * rsel + 1] * dinv;
                    float r1 = acc[mf][1][2 * rsel] * dinv;
                    float i1 = acc[mf][1][2 * rsel + 1] * dinv;
                    int cbase = colb + 4 * tig;
                    red_v4(g_h + (size_t)v * HID + cbase,
                           fmaf(cc, r0, ss * i0), fmaf(cc, i0, -ss * r0),
                           fmaf(cc, r1, ss * i1), fmaf(cc, i1, -ss * r1));
                    red_v4(g_h + (size_t)u * HID + cbase,
                           fmaf(-cc, r0, ss * i0), fmaf(-cc, i0, -ss * r0),
                           fmaf(-cc, r1, ss * i1), fmaf(-cc, i1, -ss * r1));
                }
            }
        }
        __syncthreads();   // all warps done reading A before next build
    }
}

// ---------------------------------------------------------------------------
// Stage 2 (fp16 single-pass): two-group ping-pong + tensor-phase mutex,
// 2 CTAs/SM. W tiles col-permuted -> epilogue uses STG.128 (half the store
// wavefronts); EA streamed as uint4 (LDG.128 + STS.128).
// ---------------------------------------------------------------------------
__global__ void __launch_bounds__(512, 2) stage2_kernel(
    const float* __restrict__ Wout, const float* __restrict__ Wskip,
    const float* __restrict__ bskip, const float* __restrict__ bias,
    const int* __restrict__ ei, const void* __restrict__ mraw,
    float* __restrict__ out)
{
    extern __shared__ __align__(16) char sm[];
    __shared__ int sflags[2];
    __shared__ int s_sync[3];   // [0]=turn, [1]=done grp0, [2]=done grp1
    const int tid = threadIdx.x, l = tid & 31;
    const int kind = detect_kind(mraw, sflags);
    const uint32_t sb = smem_u32(sm);
    float* bv = (float*)(sm + S_BV);

    if (tid < 3) s_sync[tid] = 0;

    for (int x = tid; x < 128 * 32; x += 512) {      // W_out: k 0..63
        int n = x >> 5, kp = x & 31;
        float2 wv = *(const float2*)(Wout + n * HID + 2 * kp);
        *(uint32_t*)(sm + W_F + (uint32_t)(permrow(n) * 400 + 4 * kp)) =
            f16x2(wv.x, wv.y);
    }
    for (int x = tid; x < 128 * 64; x += 512) {      // W_skip: k 64..191
        int n = x >> 6, kp = x & 63;
        float2 wv = *(const float2*)(Wskip + n * IN_CH + 2 * kp);
        *(uint32_t*)(sm + W_F + (uint32_t)(permrow(n) * 400 + 128 + 4 * kp)) =
            f16x2(wv.x, wv.y);
    }
    if (tid < 128) bv[tid] = bskip[tid] + bias[tid];
    __syncthreads();

    const int grp = tid >> 8;            // 0 or 1
    const int gtid = tid & 255;
    const int w8 = (tid >> 5) & 7;
    const int barid = grp + 1;
    const uint32_t aBase = sb + (uint32_t)grp * A_GRP;

    const int wr = w8 >> 2, wc = w8 & 3; // 2x4 warp grid over 64x128 output
    const int rowb = wr * 32, colb = wc * 32;
    const int g = l >> 2, tig = l & 3;
    const uint32_t a_sub = (uint32_t)((rowb + ((l >> 3) & 1) * 8 + (l & 7)) * 400
                                      + (l >> 4) * 16);
    const uint32_t b_sub = (uint32_t)((colb + ((l >> 4) & 1) * 8 + (l & 7)) * 400
                                      + ((l >> 3) & 1) * 16);

    const int t0 = blockIdx.x * 2 + grp;
    const int tstride = gridDim.x * 2;
    int pre = 0;
    if (t0 < NT2)
        pre = load_lane_meta(ei, mraw, kind, t0 * 64 + w8 * 8, l);

    for (int t = t0; t < NT2; t += tstride) {
        // ---- Phase A: gathers + uint4 EA streaming + Y build ----
        float2 phv[8], phu[8];
        #pragma unroll
        for (int r = 0; r < 8; r++) {
            int u = __shfl_sync(0xffffffffu, pre, r);
            int v = __shfl_sync(0xffffffffu, pre, r + 8);
            phv[r] = *(const float2*)(g_h + (size_t)v * HID + 2 * l);
            phu[r] = *(const float2*)(g_h + (size_t)u * HID + 2 * l);
        }
        {
            // lane covers 16B of row (2*i + (l>>4)); 4 iters cover 8 rows
            uint4 ef4[4];
            const char* efb = (const char*)g_ef;
            #pragma unroll
            for (int i = 0; i < 4; i++) {
                size_t e = (size_t)(t * 64 + w8 * 8 + 2 * i + (l >> 4));
                ef4[i] = *(const uint4*)(efb + e * 256 + (l & 15) * 16);
            }
            #pragma unroll
            for (int i = 0; i < 4; i++) {
                int r = w8 * 8 + 2 * i + (l >> 4);
                *(uint4*)(sm + (aBase - sb)
                          + (uint32_t)(r * 400 + 128 + (l & 15) * 16)) = ef4[i];
            }
        }
        #pragma unroll
        for (int rq = 0; rq < 8; rq++) {
            int r = w8 * 8 + rq;
            int u = __shfl_sync(0xffffffffu, pre, rq);
            int v = __shfl_sync(0xffffffffu, pre, rq + 8);
            int mm = __shfl_sync(0xffffffffu, pre, rq + 16);
            float cc, ss, dinv;
            if (mm) { cc = 1.0f; ss = 0.0f; dinv = (u == v) ? 0.0f : RS2; }
            else    { cc = RS2;  ss = RS2;  dinv = RS2; }
            float av = fmaxf(phv[rq].x, 0.f), bvv = fmaxf(phv[rq].y, 0.f);
            float au = fmaxf(phu[rq].x, 0.f), bu  = fmaxf(phu[rq].y, 0.f);
            float yr = dinv * (cc * (av - au) - ss * (bvv + bu));
            float yi = dinv * (cc * (bvv - bu) + ss * (av + au));
            *(uint32_t*)(sm + (aBase - sb)
                         + (uint32_t)(r * 400 + 4 * l)) = f16x2(yr, yi);
        }
        // prefetch next tile's indices (land during Phase B)
        const int tn = t + tstride;
        pre = (tn < NT2) ? load_lane_meta(ei, mraw, kind, tn * 64 + w8 * 8, l) : 0;
        bar_grp(barid);

        // ---- acquire tensor-phase ticket (perf-only mutex) ----
        if (gtid == 0) {
            volatile int* vs = s_sync;
            while (vs[0] != grp && vs[1 + (1 - grp)] == 0) { }
        }
        bar_grp(barid);

        // ---- Phase B: single-pass fp16 mma over K=192 ----
        float acc[2][4][4];
        #pragma unroll
        for (int mf = 0; mf < 2; mf++)
            #pragma unroll
            for (int nf = 0; nf < 4; nf++)
                #pragma unroll
                for (int i = 0; i < 4; i++) acc[mf][nf][i] = 0.f;

        {
            uint32_t aa0 = aBase + a_sub, aa1 = aa0 + 16 * 400;
            uint32_t bb0 = sb + W_F + b_sub, bb1 = bb0 + 16 * 400;
            #pragma unroll 4
            for (int ks = 0; ks < 12; ks++) {
                uint32_t A0[4], A1[4], B0[4], B1[4];
                LDSM4(A0, aa0);
                LDSM4(A1, aa1);
                LDSM4(B0, bb0);
                LDSM4(B1, bb1);
                mmaf16(acc[0][0], A0, B0);
                mmaf16(acc[0][1], A0, B0 + 2);
                mmaf16(acc[0][2], A0, B1);
                mmaf16(acc[0][3], A0, B1 + 2);
                mmaf16(acc[1][0], A1, B0);
                mmaf16(acc[1][1], A1, B0 + 2);
                mmaf16(acc[1][2], A1, B1);
                mmaf16(acc[1][3], A1, B1 + 2);
                aa0 += 32; aa1 += 32; bb0 += 32; bb1 += 32;
            }
        }

        // ---- release ticket ----
        if (gtid == 0) ((volatile int*)s_sync)[0] = 1 - grp;

        // ---- Phase C: bias + STG.128 stores (perm makes cols contiguous) ----
        #pragma unroll
        for (int mf = 0; mf < 2; mf++) {
            int e0 = t * 64 + rowb + mf * 16 + g;
            #pragma unroll
            for (int hb = 0; hb < 2; hb++) {
                int n0 = 2 * hb, n1 = 2 * hb + 1;
                int c = colb + hb * 16 + 4 * tig;
                float4 bb4 = *(const float4*)(bv + c);
                float4 v0, v1;
                v0.x = acc[mf][n0][0] + bb4.x;
                v0.y = acc[mf][n0][1] + bb4.y;
                v0.z = acc[mf][n1][0] + bb4.z;
                v0.w = acc[mf][n1][1] + bb4.w;
                v1.x = acc[mf][n0][2] + bb4.x;
                v1.y = acc[mf][n0][3] + bb4.y;
                v1.z = acc[mf][n1][2] + bb4.z;
                v1.w = acc[mf][n1][3] + bb4.w;
                *(float4*)(out + (size_t)e0 * OUT_CH + c) = v0;
                *(float4*)(out + (size_t)(e0 + 8) * OUT_CH + c) = v1;
            }
        }
        bar_grp(barid);   // A buffer free for next Phase A
    }

    // signal completion so the other group never waits on us again
    if (gtid == 0) ((volatile int*)s_sync)[1 + grp] = 1;
}

extern "C" void kernel_launch(void* const* d_in, const int* in_sizes, int n_in,
                              void* d_out, int out_size) {
    (void)in_sizes; (void)n_in; (void)out_size;
    const int*   ei    = (const int*)d_in[0];
    const void*  mask  = d_in[1];
    const float* ea    = (const float*)d_in[2];
    const float* Win   = (const float*)d_in[3];
    const float* Wout  = (const float*)d_in[4];
    const float* Wskip = (const float*)d_in[5];
    const float* bskip = (const float*)d_in[6];
    const float* bias  = (const float*)d_in[7];
    float* out = (float*)d_out;

    int dev = 0;
    cudaGetDevice(&dev);
    int sms = 148;
    cudaDeviceGetAttribute(&sms, cudaDevAttrMultiProcessorCount, dev);

    void* hptr = nullptr;
    cudaGetSymbolAddress(&hptr, g_h);

    cudaFuncSetAttribute(stage1_kernel,
                         cudaFuncAttributeMaxDynamicSharedMemorySize, SMEM1);
    cudaFuncSetAttribute(stage2_kernel,
                         cudaFuncAttributeMaxDynamicSharedMemorySize, SMEM2);

    cudaMemsetAsync(hptr, 0, sizeof(float) * (size_t)NN * HID);
    stage1_kernel<<<sms * 2, 512, SMEM1>>>(ea, Win, ei, mask);
    stage2_kernel<<<sms * 2, 512, SMEM2>>>(Wout, Wskip, bskip, bias, ei, mask, out);
}